// round 1
// baseline (speedup 1.0000x reference)
#include <cuda_runtime.h>

#define NU 200000
#define NR 200000
#define HDIM 64
#define EDGES 4000000
#define SCAN_B 1024

// ---------------- static device scratch (no runtime allocation) ----------------
__device__ float g_xr0[(size_t)NR * HDIM];
__device__ float g_xr1[(size_t)NR * HDIM];
__device__ float g_xu1[(size_t)NU * HDIM];
__device__ float g_xu2[(size_t)NU * HDIM];
__device__ float g_mean_r[(size_t)NR * HDIM];
__device__ float g_mean_u[(size_t)NU * HDIM];
__device__ int   g_nbr_r[EDGES];
__device__ int   g_nbr_u[EDGES];
__device__ int   g_off_u[NU + 1];
__device__ int   g_off_r[NR + 1];
__device__ int   g_deg_u[NU];
__device__ int   g_deg_r[NR];
__device__ int   g_cur_u[NU];
__device__ int   g_cur_r[NR];
__device__ int   g_bsum[SCAN_B];

// ---------------- CSR build ----------------
__global__ void k_zero_counts(int* a, int* b, int* c, int* d, int n) {
    int i = blockIdx.x * blockDim.x + threadIdx.x;
    if (i < n) { a[i] = 0; b[i] = 0; c[i] = 0; d[i] = 0; }
}

__global__ void k_count(const int* __restrict__ ei, int* __restrict__ deg_u,
                        int* __restrict__ deg_r, int e) {
    int i = blockIdx.x * blockDim.x + threadIdx.x;
    if (i < e) {
        atomicAdd(&deg_u[ei[i]], 1);       // src (user)
        atomicAdd(&deg_r[ei[e + i]], 1);   // dst (recipe)
    }
}

__global__ void k_scan1(const int* __restrict__ deg, int* __restrict__ bsum, int n) {
    __shared__ int sh[SCAN_B];
    int i = blockIdx.x * SCAN_B + threadIdx.x;
    sh[threadIdx.x] = (i < n) ? deg[i] : 0;
    __syncthreads();
    for (int s = SCAN_B / 2; s > 0; s >>= 1) {
        if (threadIdx.x < s) sh[threadIdx.x] += sh[threadIdx.x + s];
        __syncthreads();
    }
    if (threadIdx.x == 0) bsum[blockIdx.x] = sh[0];
}

__global__ void k_scan2(int* bsum, int nb) {
    __shared__ int sh[SCAN_B];
    int v = (threadIdx.x < nb) ? bsum[threadIdx.x] : 0;
    sh[threadIdx.x] = v;
    __syncthreads();
    for (int s = 1; s < SCAN_B; s <<= 1) {
        int t = (threadIdx.x >= s) ? sh[threadIdx.x - s] : 0;
        __syncthreads();
        sh[threadIdx.x] += t;
        __syncthreads();
    }
    if (threadIdx.x < nb) bsum[threadIdx.x] = sh[threadIdx.x] - v;  // exclusive
}

__global__ void k_scan3(const int* __restrict__ deg, const int* __restrict__ bsum,
                        int* __restrict__ off, int n) {
    __shared__ int sh[SCAN_B];
    int i = blockIdx.x * SCAN_B + threadIdx.x;
    int v = (i < n) ? deg[i] : 0;
    sh[threadIdx.x] = v;
    __syncthreads();
    for (int s = 1; s < SCAN_B; s <<= 1) {
        int t = (threadIdx.x >= s) ? sh[threadIdx.x - s] : 0;
        __syncthreads();
        sh[threadIdx.x] += t;
        __syncthreads();
    }
    int excl = sh[threadIdx.x] - v + bsum[blockIdx.x];
    if (i < n) off[i] = excl;
    if (i == n - 1) off[n] = excl + v;
}

__global__ void k_fill(const int* __restrict__ ei,
                       const int* __restrict__ off_u, const int* __restrict__ off_r,
                       int* __restrict__ cur_u, int* __restrict__ cur_r,
                       int* __restrict__ nbr_u, int* __restrict__ nbr_r, int e) {
    int i = blockIdx.x * blockDim.x + threadIdx.x;
    if (i < e) {
        int s = ei[i], d = ei[e + i];
        int pu = atomicAdd(&cur_u[s], 1);
        nbr_u[off_u[s] + pu] = d;
        int pr = atomicAdd(&cur_r[d], 1);
        nbr_r[off_r[d] + pr] = s;
    }
}

// ---------------- x_recipe init: recipe_x @ lin_w + lin_b + recipe_emb ----------------
__global__ void k_init_recipe(const float* __restrict__ rx, const float* __restrict__ lw,
                              const float* __restrict__ lb, const float* __restrict__ remb,
                              float* __restrict__ out, int n) {
    __shared__ float slw[640];
    __shared__ float slb[64];
    for (int i = threadIdx.x; i < 640; i += blockDim.x) slw[i] = lw[i];
    if (threadIdx.x < 64) slb[threadIdx.x] = lb[threadIdx.x];
    __syncthreads();
    int idx = blockIdx.x * blockDim.x + threadIdx.x;
    if (idx >= n * HDIM) return;
    int r = idx >> 6, h = idx & 63;
    float acc = slb[h];
#pragma unroll
    for (int k = 0; k < 10; k++) acc = fmaf(rx[r * 10 + k], slw[k * 64 + h], acc);
    out[idx] = acc + remb[idx];
}

// ---------------- mean aggregation: warp per dst node (no float atomics) ----------------
__global__ void k_aggregate(const int* __restrict__ off, const int* __restrict__ nbr,
                            const float* __restrict__ xsrc, float* __restrict__ mean, int n) {
    int w = (blockIdx.x * blockDim.x + threadIdx.x) >> 5;
    int lane = threadIdx.x & 31;
    if (w >= n) return;
    int beg = off[w], end = off[w + 1];
    const float2* X = (const float2*)xsrc;
    float vx = 0.f, vy = 0.f;
    for (int j = beg; j < end; j += 32) {
        int cnt = end - j; if (cnt > 32) cnt = 32;
        int idx = (lane < cnt) ? nbr[j + lane] : 0;
        int t = 0;
        for (; t + 4 <= cnt; t += 4) {  // MLP=4 software pipeline
            int r0 = __shfl_sync(0xffffffffu, idx, t);
            int r1 = __shfl_sync(0xffffffffu, idx, t + 1);
            int r2 = __shfl_sync(0xffffffffu, idx, t + 2);
            int r3 = __shfl_sync(0xffffffffu, idx, t + 3);
            float2 v0 = X[r0 * 32 + lane];
            float2 v1 = X[r1 * 32 + lane];
            float2 v2 = X[r2 * 32 + lane];
            float2 v3 = X[r3 * 32 + lane];
            vx += (v0.x + v1.x) + (v2.x + v3.x);
            vy += (v0.y + v1.y) + (v2.y + v3.y);
        }
        for (; t < cnt; t++) {
            int r = __shfl_sync(0xffffffffu, idx, t);
            float2 v = X[r * 32 + lane];
            vx += v.x; vy += v.y;
        }
    }
    float inv = 1.0f / fmaxf((float)(end - beg), 1.0f);
    ((float2*)mean)[w * 32 + lane] = make_float2(vx * inv, vy * inv);
}

// ---------------- transform: out = mean@Wl + bl + x@Wr (+relu) ----------------
// 64-row tile per block, 256 threads, 4x4 fp32 accumulators per thread.
// K=128 logically ([mean;x] x [Wl;Wr]) processed as two 64-K phases sharing accumulators.
__global__ void __launch_bounds__(256) k_transform(
    const float* __restrict__ A0, const float* __restrict__ A1,
    const float* __restrict__ W0, const float* __restrict__ W1,
    const float* __restrict__ bias, float* __restrict__ out, int relu) {
    __shared__ float4 sW[1024];  // 64x64
    __shared__ float4 sA[1024];  // 64 rows x 64 cols, row-major
    int t = threadIdx.x;
    int tx = t & 15;   // col quad: cols 4*tx..4*tx+3
    int ty = t >> 4;   // row quad: rows 4*ty..4*ty+3
    size_t rbase = (size_t)blockIdx.x * 64;
    float acc[4][4];
#pragma unroll
    for (int i = 0; i < 4; i++)
#pragma unroll
        for (int j = 0; j < 4; j++) acc[i][j] = 0.f;
    const float* sAf = (const float*)sA;

#pragma unroll
    for (int ph = 0; ph < 2; ph++) {
        const float4* A = (const float4*)((ph ? A1 : A0) + rbase * 64);
        const float4* W = (const float4*)(ph ? W1 : W0);
        __syncthreads();
#pragma unroll
        for (int u = 0; u < 4; u++) {
            sW[t + u * 256] = W[t + u * 256];
            sA[t + u * 256] = A[t + u * 256];
        }
        __syncthreads();
#pragma unroll 8
        for (int k = 0; k < 64; k++) {
            float4 w = sW[k * 16 + tx];
            float a0 = sAf[(ty * 4 + 0) * 64 + k];
            float a1 = sAf[(ty * 4 + 1) * 64 + k];
            float a2 = sAf[(ty * 4 + 2) * 64 + k];
            float a3 = sAf[(ty * 4 + 3) * 64 + k];
            acc[0][0] = fmaf(a0, w.x, acc[0][0]); acc[0][1] = fmaf(a0, w.y, acc[0][1]);
            acc[0][2] = fmaf(a0, w.z, acc[0][2]); acc[0][3] = fmaf(a0, w.w, acc[0][3]);
            acc[1][0] = fmaf(a1, w.x, acc[1][0]); acc[1][1] = fmaf(a1, w.y, acc[1][1]);
            acc[1][2] = fmaf(a1, w.z, acc[1][2]); acc[1][3] = fmaf(a1, w.w, acc[1][3]);
            acc[2][0] = fmaf(a2, w.x, acc[2][0]); acc[2][1] = fmaf(a2, w.y, acc[2][1]);
            acc[2][2] = fmaf(a2, w.z, acc[2][2]); acc[2][3] = fmaf(a2, w.w, acc[2][3]);
            acc[3][0] = fmaf(a3, w.x, acc[3][0]); acc[3][1] = fmaf(a3, w.y, acc[3][1]);
            acc[3][2] = fmaf(a3, w.z, acc[3][2]); acc[3][3] = fmaf(a3, w.w, acc[3][3]);
        }
    }
    float4 b = ((const float4*)bias)[tx];
#pragma unroll
    for (int i = 0; i < 4; i++) {
        float4 o = make_float4(acc[i][0] + b.x, acc[i][1] + b.y,
                               acc[i][2] + b.z, acc[i][3] + b.w);
        if (relu) {
            o.x = fmaxf(o.x, 0.f); o.y = fmaxf(o.y, 0.f);
            o.z = fmaxf(o.z, 0.f); o.w = fmaxf(o.w, 0.f);
        }
        ((float4*)(out + (rbase + (size_t)(ty * 4 + i)) * 64))[tx] = o;
    }
}

// ---------------- classifier: warp per label edge ----------------
__global__ void k_classify(const int* __restrict__ eli, const float* __restrict__ xu,
                           const float* __restrict__ xr, float* __restrict__ out, int nl) {
    int w = (blockIdx.x * blockDim.x + threadIdx.x) >> 5;
    int lane = threadIdx.x & 31;
    if (w >= nl) return;
    int a = eli[w], b = eli[nl + w];
    float2 va = ((const float2*)xu)[a * 32 + lane];
    float2 vb = ((const float2*)xr)[b * 32 + lane];
    float s = va.x * vb.x + va.y * vb.y;
#pragma unroll
    for (int o = 16; o > 0; o >>= 1) s += __shfl_down_sync(0xffffffffu, s, o);
    if (lane == 0) out[w] = s;
}

// ---------------- launch ----------------
extern "C" void kernel_launch(void* const* d_in, const int* in_sizes, int n_in,
                              void* d_out, int out_size) {
    // inputs (metadata order). user_node_id / recipe_node_id are arange -> identity gathers, unused.
    const float* recipe_x   = (const float*)d_in[2];
    const int*   edge_index = (const int*)d_in[3];
    const int*   eli        = (const int*)d_in[4];
    const float* user_emb   = (const float*)d_in[5];
    const float* recipe_emb = (const float*)d_in[6];
    const float* lin_w      = (const float*)d_in[7];
    const float* lin_b      = (const float*)d_in[8];
    const float* Wl         = (const float*)d_in[9];
    const float* bl         = (const float*)d_in[10];
    const float* Wr         = (const float*)d_in[11];
    float* out = (float*)d_out;
    int E_ = in_sizes[3] / 2;
    int L_ = in_sizes[4] / 2;

    float *xr0, *xr1, *xu1, *xu2, *mean_r, *mean_u;
    int *nbr_r, *nbr_u, *off_u, *off_r, *deg_u, *deg_r, *cur_u, *cur_r, *bsum;
    cudaGetSymbolAddress((void**)&xr0,    g_xr0);
    cudaGetSymbolAddress((void**)&xr1,    g_xr1);
    cudaGetSymbolAddress((void**)&xu1,    g_xu1);
    cudaGetSymbolAddress((void**)&xu2,    g_xu2);
    cudaGetSymbolAddress((void**)&mean_r, g_mean_r);
    cudaGetSymbolAddress((void**)&mean_u, g_mean_u);
    cudaGetSymbolAddress((void**)&nbr_r,  g_nbr_r);
    cudaGetSymbolAddress((void**)&nbr_u,  g_nbr_u);
    cudaGetSymbolAddress((void**)&off_u,  g_off_u);
    cudaGetSymbolAddress((void**)&off_r,  g_off_r);
    cudaGetSymbolAddress((void**)&deg_u,  g_deg_u);
    cudaGetSymbolAddress((void**)&deg_r,  g_deg_r);
    cudaGetSymbolAddress((void**)&cur_u,  g_cur_u);
    cudaGetSymbolAddress((void**)&cur_r,  g_cur_r);
    cudaGetSymbolAddress((void**)&bsum,   g_bsum);

    int nbu = (NU + SCAN_B - 1) / SCAN_B;  // 196

    // CSR build (once per launch; int atomics only)
    k_zero_counts<<<(NU + 255) / 256, 256>>>(deg_u, deg_r, cur_u, cur_r, NU);
    k_count<<<(E_ + 255) / 256, 256>>>(edge_index, deg_u, deg_r, E_);
    k_scan1<<<nbu, SCAN_B>>>(deg_u, bsum, NU);
    k_scan2<<<1, SCAN_B>>>(bsum, nbu);
    k_scan3<<<nbu, SCAN_B>>>(deg_u, bsum, off_u, NU);
    k_scan1<<<nbu, SCAN_B>>>(deg_r, bsum, NR);
    k_scan2<<<1, SCAN_B>>>(bsum, nbu);
    k_scan3<<<nbu, SCAN_B>>>(deg_r, bsum, off_r, NR);
    k_fill<<<(E_ + 255) / 256, 256>>>(edge_index, off_u, off_r, cur_u, cur_r, nbr_u, nbr_r, E_);

    // x_recipe init
    k_init_recipe<<<(NR * HDIM + 255) / 256, 256>>>(recipe_x, lin_w, lin_b, recipe_emb, xr0, NR);

    int aggB = (NR * 32 + 255) / 256;

    // layer 0 (relu)
    k_aggregate<<<aggB, 256>>>(off_r, nbr_r, user_emb, mean_r, NR);
    k_aggregate<<<aggB, 256>>>(off_u, nbr_u, xr0, mean_u, NU);
    k_transform<<<NR / 64, 256>>>(mean_r, xr0, Wl, Wr, bl, xr1, 1);
    k_transform<<<NU / 64, 256>>>(mean_u, user_emb, Wl + 4096, Wr + 4096, bl + 64, xu1, 1);

    // layer 1
    k_aggregate<<<aggB, 256>>>(off_r, nbr_r, xu1, mean_r, NR);
    k_aggregate<<<aggB, 256>>>(off_u, nbr_u, xr1, mean_u, NU);
    k_transform<<<NR / 64, 256>>>(mean_r, xr1, Wl + 8192, Wr + 8192, bl + 128, xr0, 0);
    k_transform<<<NU / 64, 256>>>(mean_u, xu1, Wl + 12288, Wr + 12288, bl + 192, xu2, 0);

    // classifier
    k_classify<<<(L_ * 32 + 255) / 256, 256>>>(eli, xu2, xr0, out, L_);
}